// round 3
// baseline (speedup 1.0000x reference)
#include <cuda_runtime.h>

#define NPOINTS 100000
#define BATCH   4096
#define KSEL    10
#define TILE    8192          // points per smem tile (4 SoA arrays * 32KB = 128KB)
#define NWARPS  8
#define RPW     4             // rays per warp
#define THREADS 256
#define CHUNK   128           // points per screened chunk (2 groups of 64)
#define FULLMASK 0xffffffffu

typedef unsigned long long ull;

static __device__ __forceinline__ ull fma2(ull a, ull b, ull c) {
    ull d;
    asm("fma.rn.f32x2 %0, %1, %2, %3;" : "=l"(d) : "l"(a), "l"(b), "l"(c));
    return d;
}
static __device__ __forceinline__ ull pack2(float lo, float hi) {
    ull d;
    asm("mov.b64 %0, {%1, %2};" : "=l"(d) : "f"(lo), "f"(hi));
    return d;
}
static __device__ __forceinline__ void unpack2(ull v, float& lo, float& hi) {
    asm("mov.b64 {%0, %1}, %2;" : "=f"(lo), "=f"(hi) : "l"(v));
}
static __device__ __forceinline__ float sigmoidf_(float x) {
    return 1.0f / (1.0f + expf(-x));
}

__global__ __launch_bounds__(THREADS, 1)
void gsplat_topk_kernel(const float* __restrict__ rays_o,
                        const float* __restrict__ rays_d,
                        const float* __restrict__ xyz,
                        const float* __restrict__ fdc,
                        const float* __restrict__ opacity,
                        float* __restrict__ out)
{
    extern __shared__ float sm[];
    float* Xs = sm;
    float* Ys = sm + TILE;
    float* Zs = sm + 2 * TILE;
    float* Ws = sm + 3 * TILE;

    const int tid  = threadIdx.x;
    const int lane = tid & 31;
    const int wid  = tid >> 5;
    const int ray0 = (blockIdx.x * NWARPS + wid) * RPW;

    const float POSINF = __int_as_float(0x7f800000);

    // ---- per-ray setup: packed coefficients (replicated across lanes) ----
    ull A[RPW], B[RPW], C[RPW];
    float cn2[RPW], thr[RPW];
    float hd[RPW][KSEL];
    int   hi[RPW][KSEL];
    #pragma unroll
    for (int r = 0; r < RPW; r++) {
        int ray = ray0 + r;
        float ox = rays_o[3*ray+0], oy = rays_o[3*ray+1], oz = rays_o[3*ray+2];
        float dx = rays_d[3*ray+0], dy = rays_d[3*ray+1], dz = rays_d[3*ray+2];
        float cx = fmaf(dx, 3.0f, ox);
        float cy = fmaf(dy, 3.0f, oy);
        float cz = fmaf(dz, 3.0f, oz);
        A[r] = pack2(-2.0f*cx, -2.0f*cx);
        B[r] = pack2(-2.0f*cy, -2.0f*cy);
        C[r] = pack2(-2.0f*cz, -2.0f*cz);
        cn2[r] = cx*cx + cy*cy + cz*cz;
        thr[r] = POSINF;
        #pragma unroll
        for (int j = 0; j < KSEL; j++) { hd[r][j] = POSINF; hi[r][j] = 0; }
    }

    // ---- scan all points in SoA smem tiles ----
    for (int t0 = 0; t0 < NPOINTS; t0 += TILE) {
        __syncthreads();   // previous tile fully consumed
        for (int s = tid; s < TILE; s += THREADS) {
            int g = t0 + s;
            float px = 0.f, py = 0.f, pz = 0.f, pw = POSINF;
            if (g < NPOINTS) {
                px = xyz[3*g+0]; py = xyz[3*g+1]; pz = xyz[3*g+2];
                pw = fmaf(px, px, fmaf(py, py, pz*pz));
            }
            Xs[s] = px; Ys[s] = py; Zs[s] = pz; Ws[s] = pw;
        }
        __syncthreads();

        const ull* X64 = (const ull*)Xs;
        const ull* Y64 = (const ull*)Ys;
        const ull* Z64 = (const ull*)Zs;
        const ull* W64 = (const ull*)Ws;

        for (int ch = 0; ch < TILE / CHUNK; ch++) {
            const int hb = ch * (CHUNK / 2);          // ull offset of chunk
            // group 0: points chunk_base + 2*lane + {0,1}
            // group 1: points chunk_base + 64 + 2*lane + {0,1}
            ull x0 = X64[hb + lane],      x1 = X64[hb + 32 + lane];
            ull y0 = Y64[hb + lane],      y1 = Y64[hb + 32 + lane];
            ull z0 = Z64[hb + lane],      z1 = Z64[hb + 32 + lane];
            ull w0 = W64[hb + lane],      w1 = W64[hb + 32 + lane];

            float klo[RPW][2], khi[RPW][2], lm[RPW];
            #pragma unroll
            for (int r = 0; r < RPW; r++) {
                ull k0 = fma2(x0, A[r], fma2(y0, B[r], fma2(z0, C[r], w0)));
                ull k1 = fma2(x1, A[r], fma2(y1, B[r], fma2(z1, C[r], w1)));
                unpack2(k0, klo[r][0], khi[r][0]);
                unpack2(k1, klo[r][1], khi[r][1]);
                lm[r] = fminf(fminf(klo[r][0], khi[r][0]),
                              fminf(klo[r][1], khi[r][1]));
            }

            bool trig = (lm[0] < thr[0]) | (lm[1] < thr[1]) |
                        (lm[2] < thr[2]) | (lm[3] < thr[3]);
            if (__any_sync(FULLMASK, trig)) {
                const int pbase = t0 + ch * CHUNK;
                #pragma unroll
                for (int r = 0; r < RPW; r++) {
                    unsigned mr = __ballot_sync(FULLMASK, lm[r] < thr[r]);
                    while (mr) {
                        int src = __ffs(mr) - 1;
                        mr &= mr - 1;
                        float v00 = __shfl_sync(FULLMASK, klo[r][0], src);
                        float v01 = __shfl_sync(FULLMASK, khi[r][0], src);
                        float v10 = __shfl_sync(FULLMASK, klo[r][1], src);
                        float v11 = __shfl_sync(FULLMASK, khi[r][1], src);
                        int i0 = pbase + 2 * src;
                        int i1 = pbase + 64 + 2 * src;
                        // warp-uniform convergent inserts (all lanes identical)
                        #pragma unroll
                        for (int q = 0; q < 4; q++) {
                            float kv = (q == 0) ? v00 : (q == 1) ? v01 : (q == 2) ? v10 : v11;
                            int   ki = (q == 0) ? i0  : (q == 1) ? i0+1 : (q == 2) ? i1 : i1+1;
                            if (kv < thr[r]) {
                                float v = kv; int vi = ki;
                                #pragma unroll
                                for (int jj = 0; jj < KSEL; jj++) {
                                    if (v < hd[r][jj]) {
                                        float tv = hd[r][jj]; hd[r][jj] = v;  v  = tv;
                                        int   ti = hi[r][jj]; hi[r][jj] = vi; vi = ti;
                                    }
                                }
                                thr[r] = hd[r][KSEL-1];
                            }
                        }
                    }
                }
            }
        }
    }

    // ---- epilogue: every lane holds the exact sorted top-10 per ray ----
    if (lane == 0) {
        #pragma unroll
        for (int r = 0; r < RPW; r++) {
            float ws = 0.f, s0 = 0.f, s1 = 0.f, s2 = 0.f;
            #pragma unroll
            for (int k = 0; k < KSEL; k++) {
                float sq = hd[r][k] + cn2[r];
                float dist = sqrtf(fmaxf(sq, 0.0f));
                int id = hi[r][k];
                float op = opacity[id];
                float w = expf(-0.1f * dist) * sigmoidf_(op);
                ws += w;
                float f0 = fdc[3*id+0], f1 = fdc[3*id+1], f2 = fdc[3*id+2];
                s0 = fmaf(w, sigmoidf_(f0), s0);
                s1 = fmaf(w, sigmoidf_(f1), s1);
                s2 = fmaf(w, sigmoidf_(f2), s2);
            }
            float inv = 1.0f / (ws + 1e-8f);
            int ray = ray0 + r;
            out[3*ray+0] = s0 * inv;
            out[3*ray+1] = s1 * inv;
            out[3*ray+2] = s2 * inv;
        }
    }
}

extern "C" void kernel_launch(void* const* d_in, const int* in_sizes, int n_in,
                              void* d_out, int out_size)
{
    const float* rays_o  = (const float*)d_in[0];
    const float* rays_d  = (const float*)d_in[1];
    const float* xyz     = (const float*)d_in[2];
    const float* fdc     = (const float*)d_in[3];
    const float* opacity = (const float*)d_in[4];
    float* out = (float*)d_out;

    const int smem = 4 * TILE * sizeof(float);   // 128 KB
    static bool attr_set = false;
    if (!attr_set) {
        cudaFuncSetAttribute(gsplat_topk_kernel,
                             cudaFuncAttributeMaxDynamicSharedMemorySize, smem);
        attr_set = true;
    }

    dim3 grid(BATCH / (NWARPS * RPW));   // 128 blocks
    dim3 block(THREADS);
    gsplat_topk_kernel<<<grid, block, smem>>>(rays_o, rays_d, xyz, fdc, opacity, out);
}

// round 4
// speedup vs baseline: 1.0840x; 1.0840x over previous
#include <cuda_runtime.h>

#define NPOINTS 100000
#define BATCH   4096
#define KSEL    10
#define TILE    8192
#define NWARPS  16
#define RPW     4
#define THREADS 512
#define CHUNK   128
#define NHALF   2
#define HALFPTS 50000
#define HALFPAD 50048          // 391 * 128
#define FULLMASK 0xffffffffu

typedef unsigned long long ull;

// partial top-K scratch: [half][ray][k]
__device__ float g_pd[NHALF][BATCH][KSEL];
__device__ int   g_pi[NHALF][BATCH][KSEL];

static __device__ __forceinline__ ull fma2(ull a, ull b, ull c) {
    ull d;
    asm("fma.rn.f32x2 %0, %1, %2, %3;" : "=l"(d) : "l"(a), "l"(b), "l"(c));
    return d;
}
static __device__ __forceinline__ ull pack2(float lo, float hi) {
    ull d;
    asm("mov.b64 %0, {%1, %2};" : "=l"(d) : "f"(lo), "f"(hi));
    return d;
}
static __device__ __forceinline__ void unpack2(ull v, float& lo, float& hi) {
    asm("mov.b64 {%0, %1}, %2;" : "=f"(lo), "=f"(hi) : "l"(v));
}
static __device__ __forceinline__ float sigmoidf_(float x) {
    return 1.0f / (1.0f + expf(-x));
}

// ---------------------------------------------------------------------------
// Kernel 1: scan half of the points for 64 rays per block, emit top-10 partials
// ---------------------------------------------------------------------------
__global__ __launch_bounds__(THREADS, 1)
void gsplat_scan_kernel(const float* __restrict__ rays_o,
                        const float* __restrict__ rays_d,
                        const float* __restrict__ xyz)
{
    extern __shared__ float sm[];
    float* Xs = sm;
    float* Ys = sm + TILE;
    float* Zs = sm + 2 * TILE;
    float* Ws = sm + 3 * TILE;
    // per-warp heaps (rare-path only): [warp][ray][k]
    float* Hd = sm + 4 * TILE;
    int*   Hi = (int*)(sm + 4 * TILE + NWARPS * RPW * KSEL);

    const int tid  = threadIdx.x;
    const int lane = tid & 31;
    const int wid  = tid >> 5;
    const int half = blockIdx.x & 1;
    const int ray0 = ((blockIdx.x >> 1) * NWARPS + wid) * RPW;

    const float POSINF = __int_as_float(0x7f800000);

    float* hd = Hd + (wid * RPW) * KSEL;   // this warp's heap keys
    int*   hi = Hi + (wid * RPW) * KSEL;

    // ---- per-ray packed coefficients (replicated across lanes) ----
    ull A[RPW], B[RPW], C[RPW];
    float thr[RPW];
    #pragma unroll
    for (int r = 0; r < RPW; r++) {
        int ray = ray0 + r;
        float ox = rays_o[3*ray+0], oy = rays_o[3*ray+1], oz = rays_o[3*ray+2];
        float dx = rays_d[3*ray+0], dy = rays_d[3*ray+1], dz = rays_d[3*ray+2];
        float cx = fmaf(dx, 3.0f, ox);
        float cy = fmaf(dy, 3.0f, oy);
        float cz = fmaf(dz, 3.0f, oz);
        A[r] = pack2(-2.0f*cx, -2.0f*cx);
        B[r] = pack2(-2.0f*cy, -2.0f*cy);
        C[r] = pack2(-2.0f*cz, -2.0f*cz);
        thr[r] = POSINF;
    }
    // init heaps (all lanes write same values; write-collapse is benign)
    #pragma unroll
    for (int r = 0; r < RPW; r++)
        #pragma unroll
        for (int j = 0; j < KSEL; j++) { hd[r*KSEL+j] = POSINF; hi[r*KSEL+j] = 0; }

    const int base = half * HALFPTS;
    const int hend = base + HALFPTS;

    for (int t0 = base; t0 < base + HALFPAD; t0 += TILE) {
        int tsz = min(TILE, base + HALFPAD - t0);   // 8192 or 896 (mult of 128)
        __syncthreads();
        for (int s = tid; s < tsz; s += THREADS) {
            int g = t0 + s;
            float px = 0.f, py = 0.f, pz = 0.f, pw = POSINF;
            if (g < hend) {
                px = xyz[3*g+0]; py = xyz[3*g+1]; pz = xyz[3*g+2];
                pw = fmaf(px, px, fmaf(py, py, pz*pz));
            }
            Xs[s] = px; Ys[s] = py; Zs[s] = pz; Ws[s] = pw;
        }
        __syncthreads();

        const ull* X64 = (const ull*)Xs;
        const ull* Y64 = (const ull*)Ys;
        const ull* Z64 = (const ull*)Zs;
        const ull* W64 = (const ull*)Ws;

        const int nch = tsz / CHUNK;
        for (int ch = 0; ch < nch; ch++) {
            const int hb = ch * (CHUNK / 2);
            ull x0 = X64[hb + lane], x1 = X64[hb + 32 + lane];
            ull y0 = Y64[hb + lane], y1 = Y64[hb + 32 + lane];
            ull z0 = Z64[hb + lane], z1 = Z64[hb + 32 + lane];
            ull w0 = W64[hb + lane], w1 = W64[hb + 32 + lane];

            float klo[RPW][2], khi[RPW][2], lm[RPW];
            #pragma unroll
            for (int r = 0; r < RPW; r++) {
                ull k0 = fma2(x0, A[r], fma2(y0, B[r], fma2(z0, C[r], w0)));
                ull k1 = fma2(x1, A[r], fma2(y1, B[r], fma2(z1, C[r], w1)));
                unpack2(k0, klo[r][0], khi[r][0]);
                unpack2(k1, klo[r][1], khi[r][1]);
                lm[r] = fminf(fminf(klo[r][0], khi[r][0]),
                              fminf(klo[r][1], khi[r][1]));
            }

            bool trig = (lm[0] < thr[0]) | (lm[1] < thr[1]) |
                        (lm[2] < thr[2]) | (lm[3] < thr[3]);
            if (__any_sync(FULLMASK, trig)) {
                const int pbase = t0 + ch * CHUNK;
                #pragma unroll
                for (int r = 0; r < RPW; r++) {
                    unsigned mr = __ballot_sync(FULLMASK, lm[r] < thr[r]);
                    while (mr) {
                        int src = __ffs(mr) - 1;
                        mr &= mr - 1;
                        float v00 = __shfl_sync(FULLMASK, klo[r][0], src);
                        float v01 = __shfl_sync(FULLMASK, khi[r][0], src);
                        float v10 = __shfl_sync(FULLMASK, klo[r][1], src);
                        float v11 = __shfl_sync(FULLMASK, khi[r][1], src);
                        int i0 = pbase + 2 * src;
                        int i1 = pbase + 64 + 2 * src;
                        #pragma unroll
                        for (int q = 0; q < 4; q++) {
                            float kv = (q==0)?v00:(q==1)?v01:(q==2)?v10:v11;
                            int   ki = (q==0)?i0:(q==1)?i0+1:(q==2)?i1:i1+1;
                            if (kv < thr[r]) {   // warp-uniform; smem bubble insert
                                float v = kv; int vi = ki;
                                #pragma unroll
                                for (int jj = 0; jj < KSEL; jj++) {
                                    float cur = hd[r*KSEL+jj];
                                    int   ci  = hi[r*KSEL+jj];
                                    if (v < cur) {
                                        hd[r*KSEL+jj] = v;  hi[r*KSEL+jj] = vi;
                                        v = cur; vi = ci;
                                    }
                                }
                                thr[r] = hd[r*KSEL+KSEL-1];
                            }
                        }
                    }
                }
            }
        }
    }

    // ---- write partials: lanes 0..9 each write one slot per ray ----
    if (lane < KSEL) {
        #pragma unroll
        for (int r = 0; r < RPW; r++) {
            int ray = ray0 + r;
            g_pd[half][ray][lane] = hd[r*KSEL+lane];
            g_pi[half][ray][lane] = hi[r*KSEL+lane];
        }
    }
}

// ---------------------------------------------------------------------------
// Kernel 2: merge the two partial top-10 lists per ray, run the epilogue
// ---------------------------------------------------------------------------
__global__ __launch_bounds__(256)
void gsplat_merge_kernel(const float* __restrict__ rays_o,
                         const float* __restrict__ rays_d,
                         const float* __restrict__ fdc,
                         const float* __restrict__ opacity,
                         float* __restrict__ out)
{
    int ray = blockIdx.x * blockDim.x + threadIdx.x;
    if (ray >= BATCH) return;

    const float POSINF = __int_as_float(0x7f800000);

    float ox = rays_o[3*ray+0], oy = rays_o[3*ray+1], oz = rays_o[3*ray+2];
    float dx = rays_d[3*ray+0], dy = rays_d[3*ray+1], dz = rays_d[3*ray+2];
    float cx = fmaf(dx, 3.0f, ox);
    float cy = fmaf(dy, 3.0f, oy);
    float cz = fmaf(dz, 3.0f, oz);
    float cn2 = cx*cx + cy*cy + cz*cz;

    float bd[KSEL]; int bi[KSEL];
    #pragma unroll
    for (int j = 0; j < KSEL; j++) { bd[j] = POSINF; bi[j] = 0; }

    #pragma unroll
    for (int h = 0; h < NHALF; h++) {
        #pragma unroll
        for (int k = 0; k < KSEL; k++) {
            float v = g_pd[h][ray][k];
            int  vi = g_pi[h][ray][k];
            #pragma unroll
            for (int j = 0; j < KSEL; j++) {
                if (v < bd[j]) {
                    float tv = bd[j]; bd[j] = v;  v  = tv;
                    int   ti = bi[j]; bi[j] = vi; vi = ti;
                }
            }
        }
    }

    float ws = 0.f, s0 = 0.f, s1 = 0.f, s2 = 0.f;
    #pragma unroll
    for (int k = 0; k < KSEL; k++) {
        float sq = bd[k] + cn2;
        float dist = sqrtf(fmaxf(sq, 0.0f));
        int id = bi[k];
        float op = opacity[id];
        float w = expf(-0.1f * dist) * sigmoidf_(op);
        ws += w;
        float f0 = fdc[3*id+0], f1 = fdc[3*id+1], f2 = fdc[3*id+2];
        s0 = fmaf(w, sigmoidf_(f0), s0);
        s1 = fmaf(w, sigmoidf_(f1), s1);
        s2 = fmaf(w, sigmoidf_(f2), s2);
    }
    float inv = 1.0f / (ws + 1e-8f);
    out[3*ray+0] = s0 * inv;
    out[3*ray+1] = s1 * inv;
    out[3*ray+2] = s2 * inv;
}

extern "C" void kernel_launch(void* const* d_in, const int* in_sizes, int n_in,
                              void* d_out, int out_size)
{
    const float* rays_o  = (const float*)d_in[0];
    const float* rays_d  = (const float*)d_in[1];
    const float* xyz     = (const float*)d_in[2];
    const float* fdc     = (const float*)d_in[3];
    const float* opacity = (const float*)d_in[4];
    float* out = (float*)d_out;

    const int smem = 4 * TILE * sizeof(float)
                   + 2 * NWARPS * RPW * KSEL * sizeof(float);   // 128KB + 5KB
    static bool attr_set = false;
    if (!attr_set) {
        cudaFuncSetAttribute(gsplat_scan_kernel,
                             cudaFuncAttributeMaxDynamicSharedMemorySize, smem);
        attr_set = true;
    }

    // 128 blocks: (64 ray-groups) x (2 point halves)
    gsplat_scan_kernel<<<dim3(NHALF * BATCH / (NWARPS * RPW)), dim3(THREADS), smem>>>(
        rays_o, rays_d, xyz);
    gsplat_merge_kernel<<<dim3((BATCH + 255) / 256), dim3(256)>>>(
        rays_o, rays_d, fdc, opacity, out);
}